// round 15
// baseline (speedup 1.0000x reference)
#include <cuda_runtime.h>
#include <cuda_fp16.h>
#include <cstdint>

#define NNODES 100000
#define NEDGES 1600000
#define NELEMS 12800000   // NNODES*128
#define SCAN_BLOCKS 391   // ceil(100000/256)
#define NSLICE 64

// ---------------- scratch (static device globals: allocation-free) ----------
__device__ float g_bufS[(size_t)NNODES * 128];   // self GEMM out / accumulator
__device__ __align__(16) __half g_G[(size_t)NNODES * 128];   // neigh GEMM out (fp16)
__device__ __align__(16) __half g_A[(size_t)NNODES * 128];   // activations fp16
__device__ __align__(16) __half g_Bt[3][256 * 128];  // per-layer [FCAT][128] fp16
__device__ int   g_degi[NNODES];
__device__ int   g_off[NNODES];
__device__ int   g_cursor[NNODES];
__device__ int   g_esrc[NEDGES];
__device__ volatile unsigned long long g_sstat[SCAN_BLOCKS];  // lookback status
__device__ float g_psum[2][NSLICE * 128];   // per-layer BN partial sums
__device__ float g_psq[2][NSLICE * 128];
__device__ float g_scale[128];
__device__ float g_shift[128];

// ---------------- threefry2x32 (exact JAX implementation) -------------------
__host__ __device__ __forceinline__ void tf2x32(uint32_t k0, uint32_t k1,
                                                uint32_t& x0, uint32_t& x1)
{
    const uint32_t ks0 = k0, ks1 = k1, ks2 = k0 ^ k1 ^ 0x1BD11BDAu;
    const uint32_t ks[3] = {ks0, ks1, ks2};
    const int rot0[4] = {13, 15, 26, 6};
    const int rot1[4] = {17, 29, 16, 24};
    x0 += ks0; x1 += ks1;
#pragma unroll
    for (int b = 0; b < 5; b++) {
        const int* r = (b & 1) ? rot1 : rot0;
#pragma unroll
        for (int i = 0; i < 4; i++) {
            x0 += x1;
            x1 = (x1 << r[i]) | (x1 >> (32 - r[i]));
            x1 ^= x0;
        }
        x0 += ks[(b + 1) % 3];
        x1 += ks[(b + 2) % 3] + (uint32_t)(b + 1);
    }
}

// ---------------- convert x -> fp16, plus all zero-init ----------------------
__global__ void k_cvt_x(const float* __restrict__ x)
{
    int j2 = blockIdx.x * blockDim.x + threadIdx.x;
    if (j2 < NNODES) g_degi[j2] = 0;
    if (j2 < 2 * NSLICE * 128) {
        ((float*)g_psum)[j2] = 0.f;
        ((float*)g_psq)[j2] = 0.f;
    }
    if (j2 < SCAN_BLOCKS) g_sstat[j2] = 0ull;
    if (j2 >= NELEMS / 2) return;
    float2 v = __ldg((const float2*)x + j2);
    ((__half2*)g_A)[j2] = __halves2half2(__float2half_rn(v.x), __float2half_rn(v.y));
}

// ---------------- CSR build --------------------------------------------------
__global__ void k_count_deg(const int* __restrict__ dst)
{
    int e = blockIdx.x * blockDim.x + threadIdx.x;
    if (e < NEDGES) atomicAdd(&g_degi[dst[e]], 1);
}

// single-pass decoupled-lookback exclusive scan of g_degi -> g_off/g_cursor
__global__ void k_scan_lookback()
{
    __shared__ int sm[256];
    __shared__ int s_prefix;
    const int b = blockIdx.x, t = threadIdx.x;
    const int i = b * 256 + t;
    int v = (i < NNODES) ? g_degi[i] : 0;
    sm[t] = v;
    __syncthreads();
#pragma unroll
    for (int d = 1; d < 256; d <<= 1) {
        int add = (t >= d) ? sm[t - d] : 0;
        __syncthreads();
        sm[t] += add;
        __syncthreads();
    }
    const int total = sm[255];

    if (t == 0) {
        // publish aggregate (flag=1 | value), single 64-bit store (atomic)
        g_sstat[b] = (1ull << 62) | (unsigned long long)(uint32_t)total;
        // lookback
        int pref = 0;
        int j = b - 1;
        while (j >= 0) {
            unsigned long long st;
            do { st = g_sstat[j]; } while (st < (1ull << 62));
            if (st >= (2ull << 62)) { pref += (int)(uint32_t)st; break; }
            pref += (int)(uint32_t)st;
            j--;
        }
        // publish inclusive prefix (flag=2 | value)
        g_sstat[b] = (2ull << 62) | (unsigned long long)(uint32_t)(pref + total);
        s_prefix = pref;
    }
    __syncthreads();
    int o = s_prefix + sm[t] - v;   // exclusive
    if (i < NNODES) {
        g_off[i] = o;
        g_cursor[i] = o;
    }
}

__global__ void k_scatter(const int* __restrict__ src, const int* __restrict__ dst)
{
    int e = blockIdx.x * blockDim.x + threadIdx.x;
    if (e < NEDGES) {
        int p = atomicAdd(&g_cursor[dst[e]], 1);
        g_esrc[p] = src[e];
    }
}

// ---------------- all weight concats -> transposed fp16 (one kernel) --------
__global__ void k_cat_w_all(const float* __restrict__ Ws0, const float* __restrict__ Wn0,
                            const float* __restrict__ Ws1, const float* __restrict__ Wn1,
                            const float* __restrict__ Ws2, const float* __restrict__ Wn2)
{
    int i = blockIdx.x * blockDim.x + threadIdx.x;
    if (i >= 81920) return;   // 2*(32768) + 16384
    int L, base;
    if (i < 32768)      { L = 0; base = i; }
    else if (i < 65536) { L = 1; base = i - 32768; }
    else                { L = 2; base = i - 65536; }
    int c = base >> 7, k = base & 127;
    const float *Ws, *Wn;
    int F;
    if (L == 0)      { Ws = Ws0; Wn = Wn0; F = 128; }
    else if (L == 1) { Ws = Ws1; Wn = Wn1; F = 128; }
    else             { Ws = Ws2; Wn = Wn2; F = 64; }
    float w = (c < F) ? __ldg(&Ws[k * F + c]) : __ldg(&Wn[k * F + (c - F)]);
    g_Bt[L][c * 128 + k] = __float2half_rn(w);
}

// ---------------- tensor-core GEMM (fp16 operands, fp32 accumulate) ---------
__device__ __forceinline__ void ldsm_x4(uint32_t (&r)[4], uint32_t addr)
{
    asm volatile("ldmatrix.sync.aligned.m8n8.x4.shared.b16 {%0,%1,%2,%3}, [%4];\n"
                 : "=r"(r[0]), "=r"(r[1]), "=r"(r[2]), "=r"(r[3]) : "r"(addr));
}

__device__ __forceinline__ void mma_f16(float (&d)[4], const uint32_t (&a)[4],
                                        uint32_t b0, uint32_t b1)
{
    asm volatile("mma.sync.aligned.m16n8k16.row.col.f32.f16.f16.f32 "
                 "{%0,%1,%2,%3}, {%4,%5,%6,%7}, {%8,%9}, {%0,%1,%2,%3};\n"
                 : "+f"(d[0]), "+f"(d[1]), "+f"(d[2]), "+f"(d[3])
                 : "r"(a[0]), "r"(a[1]), "r"(a[2]), "r"(a[3]), "r"(b0), "r"(b1));
}

// C[N, FCAT] = A[N,128] @ Bt^T.  A fp16, B fp16, fp32 accumulate.
// Block: 128 rows x 64 cols, 8 warps (4m x 2n).
// Cols [0,FH) -> out1 fp32 (+bias); cols [FH,FCAT) -> outG fp16.
// smem = 34816 (A) + 17408 (B) = 52224B -> 3 CTAs/SM (@<=85 regs).
template <int FCAT>
__global__ void __launch_bounds__(256, 3)
gemm_f16(const __half* __restrict__ A, const __half* __restrict__ Bt,
         const float* __restrict__ bias,
         float* __restrict__ out1, __half* __restrict__ outG)
{
    constexpr int FH = FCAT / 2;
    extern __shared__ char sm[];
    const int tid = threadIdx.x;
    const int row0 = blockIdx.x * 128;
    const int col0 = blockIdx.y * 64;

    // stage A (128 rows x 128 k fp16) and B (64 n-rows x 128 k fp16)
    {
        const uint4* gA = (const uint4*)A;
        for (int idx = tid; idx < 2048; idx += 256) {
            int r = idx >> 4, c = idx & 15;
            int gr = row0 + r;
            uint4 v = make_uint4(0u, 0u, 0u, 0u);
            if (gr < NNODES) v = __ldg(gA + (size_t)gr * 16 + c);
            *(uint4*)(sm + r * 272 + c * 16) = v;
        }
        const uint4* gB = (const uint4*)Bt;
        for (int idx = tid; idx < 1024; idx += 256) {
            int r = idx >> 4, c = idx & 15;
            *(uint4*)(sm + 34816 + r * 272 + c * 16) = __ldg(gB + (size_t)(col0 + r) * 16 + c);
        }
    }
    __syncthreads();

    const int lane = tid & 31, wid = tid >> 5;
    const int m_base = (wid & 3) * 32, n_base = (wid >> 2) * 32;
    const int g = lane >> 3, rr = lane & 7;

    uint32_t smb = (uint32_t)__cvta_generic_to_shared(sm);
    const uint32_t sA = smb, sB = smb + 34816;

    uint32_t aoff[2], boff[2];
#pragma unroll
    for (int mt = 0; mt < 2; mt++) {
        int arow = m_base + mt * 16 + (g & 1) * 8 + rr;
        aoff[mt] = (uint32_t)(arow * 272 + (g >> 1) * 16);
    }
#pragma unroll
    for (int ng = 0; ng < 2; ng++) {
        int brow = n_base + ng * 16 + (g >> 1) * 8 + rr;
        boff[ng] = (uint32_t)(brow * 272 + (g & 1) * 16);
    }

    float acc[2][4][4];
#pragma unroll
    for (int mt = 0; mt < 2; mt++)
#pragma unroll
        for (int j = 0; j < 4; j++)
#pragma unroll
            for (int q = 0; q < 4; q++) acc[mt][j][q] = 0.f;

#pragma unroll
    for (int ks = 0; ks < 8; ks++) {
        const uint32_t kb = ks * 32;
        uint32_t a[2][4], bh[2][4];
        ldsm_x4(a[0], sA + aoff[0] + kb);
        ldsm_x4(a[1], sA + aoff[1] + kb);
        ldsm_x4(bh[0], sB + boff[0] + kb);
        ldsm_x4(bh[1], sB + boff[1] + kb);
#pragma unroll
        for (int mt = 0; mt < 2; mt++) {
#pragma unroll
            for (int j = 0; j < 4; j++) {
                const int ng = j >> 1, s = (j & 1) * 2;
                mma_f16(acc[mt][j], a[mt], bh[ng][s], bh[ng][s + 1]);
            }
        }
    }

    // store: block col range is entirely within out1 (fp32) or outG (fp16)
    const bool sel = (col0 < FH);
    const int cbase = col0 - (sel ? 0 : FH);
    const int tr = lane >> 2, tc = (lane & 3) * 2;

#pragma unroll
    for (int j = 0; j < 4; j++) {
        int gc = cbase + n_base + j * 8 + tc;
        float bx = 0.f, by = 0.f;
        if (sel) { bx = __ldg(bias + gc); by = __ldg(bias + gc + 1); }
#pragma unroll
        for (int mt = 0; mt < 2; mt++) {
            int r0g = row0 + m_base + mt * 16 + tr;
            if (r0g < NNODES) {
                if (sel) {
                    float2 v = make_float2(acc[mt][j][0] + bx, acc[mt][j][1] + by);
                    *(float2*)(out1 + (size_t)r0g * FH + gc) = v;
                } else {
                    *(__half2*)(outG + (size_t)r0g * FH + gc) =
                        __floats2half2_rn(acc[mt][j][0], acc[mt][j][1]);
                }
            }
            int r1g = r0g + 8;
            if (r1g < NNODES) {
                if (sel) {
                    float2 v = make_float2(acc[mt][j][2] + bx, acc[mt][j][3] + by);
                    *(float2*)(out1 + (size_t)r1g * FH + gc) = v;
                } else {
                    *(__half2*)(outG + (size_t)r1g * FH + gc) =
                        __floats2half2_rn(acc[mt][j][2], acc[mt][j][3]);
                }
            }
        }
    }
}

// ---------------- CSR aggregation fused with BN stats (F=128) ----------------
__global__ void __launch_bounds__(256)
k_agg_csr128_stats(const __half* __restrict__ G, float* __restrict__ S, int layer)
{
    __shared__ float sm_s[1024];   // [8 warps][128 feats]
    __shared__ float sm_q[1024];

    int gid = blockIdx.x * blockDim.x + threadIdx.x;
    int n = gid >> 4;              // always < NNODES (exact grid)
    int lane = threadIdx.x & 15;
    int cnt = g_degi[n];
    int beg = g_off[n];

    float a[8];
#pragma unroll
    for (int q = 0; q < 8; q++) a[q] = 0.f;

    for (int i = beg; i < beg + cnt; i++) {
        int s = __ldg(&g_esrc[i]);
        uint4 v = __ldg((const uint4*)(G + (size_t)s * 128) + lane);
        const __half2* hp = (const __half2*)&v;
#pragma unroll
        for (int q = 0; q < 4; q++) {
            float2 f = __half22float2(hp[q]);
            a[q * 2] += f.x;
            a[q * 2 + 1] += f.y;
        }
    }

    float4* p = (float4*)(S + (size_t)n * 128 + lane * 8);
    float4 c0 = p[0], c1 = p[1];
    if (cnt > 0) {
        float w = 1.0f / (float)cnt;
        c0.x = fmaf(a[0], w, c0.x); c0.y = fmaf(a[1], w, c0.y);
        c0.z = fmaf(a[2], w, c0.z); c0.w = fmaf(a[3], w, c0.w);
        c1.x = fmaf(a[4], w, c1.x); c1.y = fmaf(a[5], w, c1.y);
        c1.z = fmaf(a[6], w, c1.z); c1.w = fmaf(a[7], w, c1.w);
        p[0] = c0; p[1] = c1;
    }

    // BN stats: combine the 2 nodes per warp, stage per-warp slabs, reduce
    float sv[8] = {c0.x, c0.y, c0.z, c0.w, c1.x, c1.y, c1.z, c1.w};
    float qv[8];
#pragma unroll
    for (int q = 0; q < 8; q++) qv[q] = sv[q] * sv[q];
#pragma unroll
    for (int q = 0; q < 8; q++) {
        sv[q] += __shfl_xor_sync(0xffffffffu, sv[q], 16);
        qv[q] += __shfl_xor_sync(0xffffffffu, qv[q], 16);
    }
    int w = threadIdx.x >> 5;
    if ((threadIdx.x & 16) == 0) {
#pragma unroll
        for (int q = 0; q < 8; q++) {
            sm_s[w * 128 + lane * 8 + q] = sv[q];
            sm_q[w * 128 + lane * 8 + q] = qv[q];
        }
    }
    __syncthreads();
    if (threadIdx.x < 128) {
        float s = 0.f, q = 0.f;
#pragma unroll
        for (int ww = 0; ww < 8; ww++) {
            s += sm_s[ww * 128 + threadIdx.x];
            q += sm_q[ww * 128 + threadIdx.x];
        }
        int slice = blockIdx.x & (NSLICE - 1);
        atomicAdd(&g_psum[layer][slice * 128 + threadIdx.x], s);
        atomicAdd(&g_psq[layer][slice * 128 + threadIdx.x], q);
    }
}

// plain F=64 aggregation (no BN on layer 2). 8 lanes/node.
__global__ void __launch_bounds__(256)
k_agg_csr64(const __half* __restrict__ G, float* __restrict__ S)
{
    int gid = blockIdx.x * blockDim.x + threadIdx.x;
    int n = gid >> 3;
    if (n >= NNODES) return;
    int lane = threadIdx.x & 7;
    int cnt = g_degi[n];
    if (cnt == 0) return;
    int beg = g_off[n], end = beg + cnt;

    float a[8];
#pragma unroll
    for (int q = 0; q < 8; q++) a[q] = 0.f;

    for (int i = beg; i < end; i++) {
        int s = __ldg(&g_esrc[i]);
        uint4 v = __ldg((const uint4*)(G + (size_t)s * 64) + lane);
        const __half2* hp = (const __half2*)&v;
#pragma unroll
        for (int q = 0; q < 4; q++) {
            float2 f = __half22float2(hp[q]);
            a[q * 2] += f.x;
            a[q * 2 + 1] += f.y;
        }
    }
    float w = 1.0f / (float)cnt;
    float4* p = (float4*)(S + (size_t)n * 64 + lane * 8);
    float4 c0 = p[0], c1 = p[1];
    c0.x = fmaf(a[0], w, c0.x); c0.y = fmaf(a[1], w, c0.y);
    c0.z = fmaf(a[2], w, c0.z); c0.w = fmaf(a[3], w, c0.w);
    c1.x = fmaf(a[4], w, c1.x); c1.y = fmaf(a[5], w, c1.y);
    c1.z = fmaf(a[6], w, c1.z); c1.w = fmaf(a[7], w, c1.w);
    p[0] = c0; p[1] = c1;
}

// ---------------- batchnorm finalize ------------------------------------------
__global__ void k_bn_finalize(const float* __restrict__ gamma, const float* __restrict__ beta,
                              int layer)
{
    int f = threadIdx.x;
    float s = 0.f, q = 0.f;
#pragma unroll 8
    for (int w = 0; w < NSLICE; w++) {
        s += g_psum[layer][w * 128 + f];
        q += g_psq[layer][w * 128 + f];
    }
    float mu = s * (1.0f / NNODES);
    float var = fmaxf(q * (1.0f / NNODES) - mu * mu, 0.f);
    float sc = gamma[f] * rsqrtf(var + 1e-5f);
    g_scale[f] = sc;
    g_shift[f] = beta[f] - mu * sc;
}

// ---------------- fused BN * ReLU * dropout -> fp16 ---------------------------
__global__ void k_bn_relu_drop(const float* __restrict__ S,
                               uint32_t k0, uint32_t k1)
{
    int j2 = blockIdx.x * blockDim.x + threadIdx.x;
    if (j2 >= NELEMS / 2) return;
    int j = j2 * 2;
    uint32_t x0 = 0u, x1 = (uint32_t)j;
    tf2x32(k0, k1, x0, x1);
    uint32_t y0 = 0u, y1 = (uint32_t)(j + 1);
    tf2x32(k0, k1, y0, y1);
    int f = j & 127;
    float2 s = __ldg((const float2*)S + j2);
    float v0 = fmaxf(fmaf(s.x, g_scale[f], g_shift[f]), 0.f) * 2.0f;
    float v1 = fmaxf(fmaf(s.y, g_scale[f + 1], g_shift[f + 1]), 0.f) * 2.0f;
    v0 = ((x0 ^ x1) >> 31) ? v0 : 0.f;
    v1 = ((y0 ^ y1) >> 31) ? v1 : 0.f;
    ((__half2*)g_A)[j2] = __halves2half2(__float2half_rn(v0), __float2half_rn(v1));
}

// ---------------- driver -----------------------------------------------------
extern "C" void kernel_launch(void* const* d_in, const int* in_sizes, int n_in,
                              void* d_out, int out_size)
{
    const float* x   = (const float*)d_in[0];
    const int*   src = (const int*)d_in[1];
    const int*   dst = (const int*)d_in[2];
    const float* Ws0 = (const float*)d_in[3];
    const float* Wn0 = (const float*)d_in[4];
    const float* b0  = (const float*)d_in[5];
    const float* ga0 = (const float*)d_in[6];
    const float* be0 = (const float*)d_in[7];
    const float* Ws1 = (const float*)d_in[8];
    const float* Wn1 = (const float*)d_in[9];
    const float* b1  = (const float*)d_in[10];
    const float* ga1 = (const float*)d_in[11];
    const float* be1 = (const float*)d_in[12];
    const float* Ws2 = (const float*)d_in[13];
    const float* Wn2 = (const float*)d_in[14];
    const float* b2  = (const float*)d_in[15];
    float* out = (float*)d_out;

    // dropout keys (partitionable threefry, foldlike split)
    uint32_t k00 = 0u, k01 = 0u; tf2x32(0u, 42u, k00, k01);
    uint32_t k10 = 0u, k11 = 1u; tf2x32(0u, 42u, k10, k11);

    float *pS;
    __half *pA, *pG, *pBt;
    cudaGetSymbolAddress((void**)&pS, g_bufS);
    cudaGetSymbolAddress((void**)&pA, g_A);
    cudaGetSymbolAddress((void**)&pG, g_G);
    cudaGetSymbolAddress((void**)&pBt, g_Bt);

    const int SMEM = 52224;
    cudaFuncSetAttribute(gemm_f16<256>, cudaFuncAttributeMaxDynamicSharedMemorySize, SMEM);
    cudaFuncSetAttribute(gemm_f16<128>, cudaFuncAttributeMaxDynamicSharedMemorySize, SMEM);

    const int GRID_E256 = (NEDGES + 255) / 256;
    const dim3 GG256((NNODES + 127) / 128, 4);
    const dim3 GG128((NNODES + 127) / 128, 2);
    const int AGG128_GRID = NNODES * 16 / 256;   // 6250, exact
    const int AGG64_GRID  = NNODES * 8 / 256;    // 3125, exact
    const int DROP_GRID = (NELEMS / 2 + 255) / 256;

    // ---- front half ordered so gemm<256> is the 4th launch (ncu) ----
    k_cvt_x<<<DROP_GRID, 256>>>(x);                                    // 1 (zero degi/psums/sstat)
    k_cat_w_all<<<(81920 + 255) / 256, 256>>>(Ws0, Wn0, Ws1, Wn1, Ws2, Wn2);  // 2
    k_count_deg<<<GRID_E256, 256>>>(dst);                              // 3
    gemm_f16<256><<<GG256, 256, SMEM>>>(pA, pBt, b0, pS, pG);          // 4 (profiled)

    // ---- CSR build remainder ----
    k_scan_lookback<<<SCAN_BLOCKS, 256>>>();
    k_scatter<<<GRID_E256, 256>>>(src, dst);

    // ---- layer 0 tail ----
    k_agg_csr128_stats<<<AGG128_GRID, 256>>>(pG, pS, 0);
    k_bn_finalize<<<1, 128>>>(ga0, be0, 0);
    k_bn_relu_drop<<<DROP_GRID, 256>>>(pS, k00, k01);

    // ---- layer 1 ----
    gemm_f16<256><<<GG256, 256, SMEM>>>(pA, pBt + 32768, b1, pS, pG);
    k_agg_csr128_stats<<<AGG128_GRID, 256>>>(pG, pS, 1);
    k_bn_finalize<<<1, 128>>>(ga1, be1, 1);
    k_bn_relu_drop<<<DROP_GRID, 256>>>(pS, k10, k11);

    // ---- layer 2 (no BN / dropout), self-part straight to d_out ----
    gemm_f16<128><<<GG128, 256, SMEM>>>(pA, pBt + 65536, b2, out, pG);
    k_agg_csr64<<<AGG64_GRID, 256>>>(pG, out);
}

// round 16
// speedup vs baseline: 1.0094x; 1.0094x over previous
#include <cuda_runtime.h>
#include <cuda_fp16.h>
#include <cstdint>

#define NNODES 100000
#define NEDGES 1600000
#define NELEMS 12800000   // NNODES*128
#define SCAN_BLOCKS 391   // ceil(100000/256)
#define NSLICE 64

// ---------------- scratch (static device globals: allocation-free) ----------
__device__ float g_bufS[(size_t)NNODES * 128];   // self GEMM out / accumulator
__device__ __align__(16) __half g_G[(size_t)NNODES * 128];   // neigh GEMM out (fp16)
__device__ __align__(16) __half g_A[(size_t)NNODES * 128];   // activations fp16
__device__ __align__(16) __half g_Bt[3][256 * 128];  // per-layer [FCAT][128] fp16
__device__ int   g_degi[NNODES];
__device__ int   g_off[NNODES];
__device__ int   g_cursor[NNODES];
__device__ int   g_esrc[NEDGES];
__device__ int   g_bsum[512];
__device__ int   g_boff[512];
__device__ float g_psum[2][NSLICE * 128];   // per-layer BN partial sums
__device__ float g_psq[2][NSLICE * 128];
__device__ float g_scale[128];
__device__ float g_shift[128];

// ---------------- threefry2x32 (exact JAX implementation) -------------------
__host__ __device__ __forceinline__ void tf2x32(uint32_t k0, uint32_t k1,
                                                uint32_t& x0, uint32_t& x1)
{
    const uint32_t ks0 = k0, ks1 = k1, ks2 = k0 ^ k1 ^ 0x1BD11BDAu;
    const uint32_t ks[3] = {ks0, ks1, ks2};
    const int rot0[4] = {13, 15, 26, 6};
    const int rot1[4] = {17, 29, 16, 24};
    x0 += ks0; x1 += ks1;
#pragma unroll
    for (int b = 0; b < 5; b++) {
        const int* r = (b & 1) ? rot1 : rot0;
#pragma unroll
        for (int i = 0; i < 4; i++) {
            x0 += x1;
            x1 = (x1 << r[i]) | (x1 >> (32 - r[i]));
            x1 ^= x0;
        }
        x0 += ks[(b + 1) % 3];
        x1 += ks[(b + 2) % 3] + (uint32_t)(b + 1);
    }
}

// ---------------- convert x -> fp16, plus all zero-init ----------------------
__global__ void k_cvt_x(const float* __restrict__ x)
{
    int j2 = blockIdx.x * blockDim.x + threadIdx.x;
    if (j2 < NNODES) g_degi[j2] = 0;
    if (j2 < 2 * NSLICE * 128) {
        ((float*)g_psum)[j2] = 0.f;
        ((float*)g_psq)[j2] = 0.f;
    }
    if (j2 >= NELEMS / 2) return;
    float2 v = __ldg((const float2*)x + j2);
    ((__half2*)g_A)[j2] = __halves2half2(__float2half_rn(v.x), __float2half_rn(v.y));
}

// ---------------- CSR build --------------------------------------------------
__global__ void k_count_deg(const int* __restrict__ dst)
{
    int e = blockIdx.x * blockDim.x + threadIdx.x;
    if (e < NEDGES) atomicAdd(&g_degi[dst[e]], 1);
}

__global__ void k_scan1()
{
    __shared__ int sm[256];
    int b = blockIdx.x, t = threadIdx.x, i = b * 256 + t;
    int v = (i < NNODES) ? g_degi[i] : 0;
    sm[t] = v;
    __syncthreads();
#pragma unroll
    for (int d = 1; d < 256; d <<= 1) {
        int add = (t >= d) ? sm[t - d] : 0;
        __syncthreads();
        sm[t] += add;
        __syncthreads();
    }
    if (i < NNODES) g_off[i] = sm[t] - v;
    if (t == 255) g_bsum[b] = sm[255];
}

__global__ void k_scan2()
{
    __shared__ int sm[512];
    int t = threadIdx.x;
    int v = (t < SCAN_BLOCKS) ? g_bsum[t] : 0;
    sm[t] = v;
    __syncthreads();
#pragma unroll
    for (int d = 1; d < 512; d <<= 1) {
        int add = (t >= d) ? sm[t - d] : 0;
        __syncthreads();
        sm[t] += add;
        __syncthreads();
    }
    g_boff[t] = sm[t] - v;
}

__global__ void k_scan3()
{
    int i = blockIdx.x * blockDim.x + threadIdx.x;
    if (i < NNODES) {
        int o = g_off[i] + g_boff[i >> 8];
        g_off[i] = o;
        g_cursor[i] = o;
    }
}

__global__ void k_scatter(const int* __restrict__ src, const int* __restrict__ dst)
{
    int e = blockIdx.x * blockDim.x + threadIdx.x;
    if (e < NEDGES) {
        int p = atomicAdd(&g_cursor[dst[e]], 1);
        g_esrc[p] = src[e];
    }
}

// ---------------- all weight concats -> transposed fp16 (one kernel) --------
__global__ void k_cat_w_all(const float* __restrict__ Ws0, const float* __restrict__ Wn0,
                            const float* __restrict__ Ws1, const float* __restrict__ Wn1,
                            const float* __restrict__ Ws2, const float* __restrict__ Wn2)
{
    int i = blockIdx.x * blockDim.x + threadIdx.x;
    if (i >= 81920) return;   // 2*(32768) + 16384
    int L, base;
    if (i < 32768)      { L = 0; base = i; }
    else if (i < 65536) { L = 1; base = i - 32768; }
    else                { L = 2; base = i - 65536; }
    int c = base >> 7, k = base & 127;
    const float *Ws, *Wn;
    int F;
    if (L == 0)      { Ws = Ws0; Wn = Wn0; F = 128; }
    else if (L == 1) { Ws = Ws1; Wn = Wn1; F = 128; }
    else             { Ws = Ws2; Wn = Wn2; F = 64; }
    float w = (c < F) ? __ldg(&Ws[k * F + c]) : __ldg(&Wn[k * F + (c - F)]);
    g_Bt[L][c * 128 + k] = __float2half_rn(w);
}

// ---------------- tensor-core GEMM (fp16 operands, fp32 accumulate) ---------
__device__ __forceinline__ void ldsm_x4(uint32_t (&r)[4], uint32_t addr)
{
    asm volatile("ldmatrix.sync.aligned.m8n8.x4.shared.b16 {%0,%1,%2,%3}, [%4];\n"
                 : "=r"(r[0]), "=r"(r[1]), "=r"(r[2]), "=r"(r[3]) : "r"(addr));
}

__device__ __forceinline__ void mma_f16(float (&d)[4], const uint32_t (&a)[4],
                                        uint32_t b0, uint32_t b1)
{
    asm volatile("mma.sync.aligned.m16n8k16.row.col.f32.f16.f16.f32 "
                 "{%0,%1,%2,%3}, {%4,%5,%6,%7}, {%8,%9}, {%0,%1,%2,%3};\n"
                 : "+f"(d[0]), "+f"(d[1]), "+f"(d[2]), "+f"(d[3])
                 : "r"(a[0]), "r"(a[1]), "r"(a[2]), "r"(a[3]), "r"(b0), "r"(b1));
}

// C[N, FCAT] = A[N,128] @ Bt^T.  A fp16, B fp16, fp32 accumulate.
// Block: 128 rows x 64 cols, 8 warps (4m x 2n).
// Cols [0,FH) -> out1 fp32 (+bias); cols [FH,FCAT) -> outG fp16.
// smem = 34816 (A) + 17408 (B) = 52224B -> 3 CTAs/SM (@<=85 regs).
template <int FCAT>
__global__ void __launch_bounds__(256, 3)
gemm_f16(const __half* __restrict__ A, const __half* __restrict__ Bt,
         const float* __restrict__ bias,
         float* __restrict__ out1, __half* __restrict__ outG)
{
    constexpr int FH = FCAT / 2;
    extern __shared__ char sm[];
    const int tid = threadIdx.x;
    const int row0 = blockIdx.x * 128;
    const int col0 = blockIdx.y * 64;

    // stage A (128 rows x 128 k fp16) and B (64 n-rows x 128 k fp16)
    {
        const uint4* gA = (const uint4*)A;
        for (int idx = tid; idx < 2048; idx += 256) {
            int r = idx >> 4, c = idx & 15;
            int gr = row0 + r;
            uint4 v = make_uint4(0u, 0u, 0u, 0u);
            if (gr < NNODES) v = __ldg(gA + (size_t)gr * 16 + c);
            *(uint4*)(sm + r * 272 + c * 16) = v;
        }
        const uint4* gB = (const uint4*)Bt;
        for (int idx = tid; idx < 1024; idx += 256) {
            int r = idx >> 4, c = idx & 15;
            *(uint4*)(sm + 34816 + r * 272 + c * 16) = __ldg(gB + (size_t)(col0 + r) * 16 + c);
        }
    }
    __syncthreads();

    const int lane = tid & 31, wid = tid >> 5;
    const int m_base = (wid & 3) * 32, n_base = (wid >> 2) * 32;
    const int g = lane >> 3, rr = lane & 7;

    uint32_t smb = (uint32_t)__cvta_generic_to_shared(sm);
    const uint32_t sA = smb, sB = smb + 34816;

    uint32_t aoff[2], boff[2];
#pragma unroll
    for (int mt = 0; mt < 2; mt++) {
        int arow = m_base + mt * 16 + (g & 1) * 8 + rr;
        aoff[mt] = (uint32_t)(arow * 272 + (g >> 1) * 16);
    }
#pragma unroll
    for (int ng = 0; ng < 2; ng++) {
        int brow = n_base + ng * 16 + (g >> 1) * 8 + rr;
        boff[ng] = (uint32_t)(brow * 272 + (g & 1) * 16);
    }

    float acc[2][4][4];
#pragma unroll
    for (int mt = 0; mt < 2; mt++)
#pragma unroll
        for (int j = 0; j < 4; j++)
#pragma unroll
            for (int q = 0; q < 4; q++) acc[mt][j][q] = 0.f;

#pragma unroll
    for (int ks = 0; ks < 8; ks++) {
        const uint32_t kb = ks * 32;
        uint32_t a[2][4], bh[2][4];
        ldsm_x4(a[0], sA + aoff[0] + kb);
        ldsm_x4(a[1], sA + aoff[1] + kb);
        ldsm_x4(bh[0], sB + boff[0] + kb);
        ldsm_x4(bh[1], sB + boff[1] + kb);
#pragma unroll
        for (int mt = 0; mt < 2; mt++) {
#pragma unroll
            for (int j = 0; j < 4; j++) {
                const int ng = j >> 1, s = (j & 1) * 2;
                mma_f16(acc[mt][j], a[mt], bh[ng][s], bh[ng][s + 1]);
            }
        }
    }

    // store: block col range is entirely within out1 (fp32) or outG (fp16)
    const bool sel = (col0 < FH);
    const int cbase = col0 - (sel ? 0 : FH);
    const int tr = lane >> 2, tc = (lane & 3) * 2;

#pragma unroll
    for (int j = 0; j < 4; j++) {
        int gc = cbase + n_base + j * 8 + tc;
        float bx = 0.f, by = 0.f;
        if (sel) { bx = __ldg(bias + gc); by = __ldg(bias + gc + 1); }
#pragma unroll
        for (int mt = 0; mt < 2; mt++) {
            int r0g = row0 + m_base + mt * 16 + tr;
            if (r0g < NNODES) {
                if (sel) {
                    float2 v = make_float2(acc[mt][j][0] + bx, acc[mt][j][1] + by);
                    *(float2*)(out1 + (size_t)r0g * FH + gc) = v;
                } else {
                    *(__half2*)(outG + (size_t)r0g * FH + gc) =
                        __floats2half2_rn(acc[mt][j][0], acc[mt][j][1]);
                }
            }
            int r1g = r0g + 8;
            if (r1g < NNODES) {
                if (sel) {
                    float2 v = make_float2(acc[mt][j][2] + bx, acc[mt][j][3] + by);
                    *(float2*)(out1 + (size_t)r1g * FH + gc) = v;
                } else {
                    *(__half2*)(outG + (size_t)r1g * FH + gc) =
                        __floats2half2_rn(acc[mt][j][2], acc[mt][j][3]);
                }
            }
        }
    }
}

// ---------------- CSR aggregation fused with BN stats (F=128) ----------------
__global__ void __launch_bounds__(256)
k_agg_csr128_stats(const __half* __restrict__ G, float* __restrict__ S, int layer)
{
    __shared__ float sm_s[1024];   // [8 warps][128 feats]
    __shared__ float sm_q[1024];

    int gid = blockIdx.x * blockDim.x + threadIdx.x;
    int n = gid >> 4;              // always < NNODES (exact grid)
    int lane = threadIdx.x & 15;
    int cnt = g_degi[n];
    int beg = g_off[n];

    float a[8];
#pragma unroll
    for (int q = 0; q < 8; q++) a[q] = 0.f;

    for (int i = beg; i < beg + cnt; i++) {
        int s = __ldg(&g_esrc[i]);
        uint4 v = __ldg((const uint4*)(G + (size_t)s * 128) + lane);
        const __half2* hp = (const __half2*)&v;
#pragma unroll
        for (int q = 0; q < 4; q++) {
            float2 f = __half22float2(hp[q]);
            a[q * 2] += f.x;
            a[q * 2 + 1] += f.y;
        }
    }

    float4* p = (float4*)(S + (size_t)n * 128 + lane * 8);
    float4 c0 = p[0], c1 = p[1];
    if (cnt > 0) {
        float w = 1.0f / (float)cnt;
        c0.x = fmaf(a[0], w, c0.x); c0.y = fmaf(a[1], w, c0.y);
        c0.z = fmaf(a[2], w, c0.z); c0.w = fmaf(a[3], w, c0.w);
        c1.x = fmaf(a[4], w, c1.x); c1.y = fmaf(a[5], w, c1.y);
        c1.z = fmaf(a[6], w, c1.z); c1.w = fmaf(a[7], w, c1.w);
        p[0] = c0; p[1] = c1;
    }

    // BN stats: combine the 2 nodes per warp, stage per-warp slabs, reduce
    float sv[8] = {c0.x, c0.y, c0.z, c0.w, c1.x, c1.y, c1.z, c1.w};
    float qv[8];
#pragma unroll
    for (int q = 0; q < 8; q++) qv[q] = sv[q] * sv[q];
#pragma unroll
    for (int q = 0; q < 8; q++) {
        sv[q] += __shfl_xor_sync(0xffffffffu, sv[q], 16);
        qv[q] += __shfl_xor_sync(0xffffffffu, qv[q], 16);
    }
    int w = threadIdx.x >> 5;
    if ((threadIdx.x & 16) == 0) {
#pragma unroll
        for (int q = 0; q < 8; q++) {
            sm_s[w * 128 + lane * 8 + q] = sv[q];
            sm_q[w * 128 + lane * 8 + q] = qv[q];
        }
    }
    __syncthreads();
    if (threadIdx.x < 128) {
        float s = 0.f, q = 0.f;
#pragma unroll
        for (int ww = 0; ww < 8; ww++) {
            s += sm_s[ww * 128 + threadIdx.x];
            q += sm_q[ww * 128 + threadIdx.x];
        }
        int slice = blockIdx.x & (NSLICE - 1);
        atomicAdd(&g_psum[layer][slice * 128 + threadIdx.x], s);
        atomicAdd(&g_psq[layer][slice * 128 + threadIdx.x], q);
    }
}

// plain F=64 aggregation (no BN on layer 2). 8 lanes/node.
__global__ void __launch_bounds__(256)
k_agg_csr64(const __half* __restrict__ G, float* __restrict__ S)
{
    int gid = blockIdx.x * blockDim.x + threadIdx.x;
    int n = gid >> 3;
    if (n >= NNODES) return;
    int lane = threadIdx.x & 7;
    int cnt = g_degi[n];
    if (cnt == 0) return;
    int beg = g_off[n], end = beg + cnt;

    float a[8];
#pragma unroll
    for (int q = 0; q < 8; q++) a[q] = 0.f;

    for (int i = beg; i < end; i++) {
        int s = __ldg(&g_esrc[i]);
        uint4 v = __ldg((const uint4*)(G + (size_t)s * 64) + lane);
        const __half2* hp = (const __half2*)&v;
#pragma unroll
        for (int q = 0; q < 4; q++) {
            float2 f = __half22float2(hp[q]);
            a[q * 2] += f.x;
            a[q * 2 + 1] += f.y;
        }
    }
    float w = 1.0f / (float)cnt;
    float4* p = (float4*)(S + (size_t)n * 64 + lane * 8);
    float4 c0 = p[0], c1 = p[1];
    c0.x = fmaf(a[0], w, c0.x); c0.y = fmaf(a[1], w, c0.y);
    c0.z = fmaf(a[2], w, c0.z); c0.w = fmaf(a[3], w, c0.w);
    c1.x = fmaf(a[4], w, c1.x); c1.y = fmaf(a[5], w, c1.y);
    c1.z = fmaf(a[6], w, c1.z); c1.w = fmaf(a[7], w, c1.w);
    p[0] = c0; p[1] = c1;
}

// ---------------- batchnorm finalize ------------------------------------------
__global__ void k_bn_finalize(const float* __restrict__ gamma, const float* __restrict__ beta,
                              int layer)
{
    int f = threadIdx.x;
    float s = 0.f, q = 0.f;
#pragma unroll 8
    for (int w = 0; w < NSLICE; w++) {
        s += g_psum[layer][w * 128 + f];
        q += g_psq[layer][w * 128 + f];
    }
    float mu = s * (1.0f / NNODES);
    float var = fmaxf(q * (1.0f / NNODES) - mu * mu, 0.f);
    float sc = gamma[f] * rsqrtf(var + 1e-5f);
    g_scale[f] = sc;
    g_shift[f] = beta[f] - mu * sc;
}

// ---------------- fused BN * ReLU * dropout -> fp16 ---------------------------
__global__ void k_bn_relu_drop(const float* __restrict__ S,
                               uint32_t k0, uint32_t k1)
{
    int j2 = blockIdx.x * blockDim.x + threadIdx.x;
    if (j2 >= NELEMS / 2) return;
    int j = j2 * 2;
    uint32_t x0 = 0u, x1 = (uint32_t)j;
    tf2x32(k0, k1, x0, x1);
    uint32_t y0 = 0u, y1 = (uint32_t)(j + 1);
    tf2x32(k0, k1, y0, y1);
    int f = j & 127;
    float2 s = __ldg((const float2*)S + j2);
    float v0 = fmaxf(fmaf(s.x, g_scale[f], g_shift[f]), 0.f) * 2.0f;
    float v1 = fmaxf(fmaf(s.y, g_scale[f + 1], g_shift[f + 1]), 0.f) * 2.0f;
    v0 = ((x0 ^ x1) >> 31) ? v0 : 0.f;
    v1 = ((y0 ^ y1) >> 31) ? v1 : 0.f;
    ((__half2*)g_A)[j2] = __halves2half2(__float2half_rn(v0), __float2half_rn(v1));
}

// ---------------- driver -----------------------------------------------------
extern "C" void kernel_launch(void* const* d_in, const int* in_sizes, int n_in,
                              void* d_out, int out_size)
{
    const float* x   = (const float*)d_in[0];
    const int*   src = (const int*)d_in[1];
    const int*   dst = (const int*)d_in[2];
    const float* Ws0 = (const float*)d_in[3];
    const float* Wn0 = (const float*)d_in[4];
    const float* b0  = (const float*)d_in[5];
    const float* ga0 = (const float*)d_in[6];
    const float* be0 = (const float*)d_in[7];
    const float* Ws1 = (const float*)d_in[8];
    const float* Wn1 = (const float*)d_in[9];
    const float* b1  = (const float*)d_in[10];
    const float* ga1 = (const float*)d_in[11];
    const float* be1 = (const float*)d_in[12];
    const float* Ws2 = (const float*)d_in[13];
    const float* Wn2 = (const float*)d_in[14];
    const float* b2  = (const float*)d_in[15];
    float* out = (float*)d_out;

    // dropout keys (partitionable threefry, foldlike split)
    uint32_t k00 = 0u, k01 = 0u; tf2x32(0u, 42u, k00, k01);
    uint32_t k10 = 0u, k11 = 1u; tf2x32(0u, 42u, k10, k11);

    float *pS;
    __half *pA, *pG, *pBt;
    cudaGetSymbolAddress((void**)&pS, g_bufS);
    cudaGetSymbolAddress((void**)&pA, g_A);
    cudaGetSymbolAddress((void**)&pG, g_G);
    cudaGetSymbolAddress((void**)&pBt, g_Bt);

    const int SMEM = 52224;
    cudaFuncSetAttribute(gemm_f16<256>, cudaFuncAttributeMaxDynamicSharedMemorySize, SMEM);
    cudaFuncSetAttribute(gemm_f16<128>, cudaFuncAttributeMaxDynamicSharedMemorySize, SMEM);

    const int GRID_E256 = (NEDGES + 255) / 256;
    const dim3 GG256((NNODES + 127) / 128, 4);
    const dim3 GG128((NNODES + 127) / 128, 2);
    const int AGG128_GRID = NNODES * 16 / 256;   // 6250, exact
    const int AGG64_GRID  = NNODES * 8 / 256;    // 3125, exact
    const int DROP_GRID = (NELEMS / 2 + 255) / 256;

    // ---- front half ordered so gemm<256> is the 4th launch (ncu) ----
    k_cvt_x<<<DROP_GRID, 256>>>(x);                                    // 1 (zero degi/psums)
    k_cat_w_all<<<(81920 + 255) / 256, 256>>>(Ws0, Wn0, Ws1, Wn1, Ws2, Wn2);  // 2
    k_count_deg<<<GRID_E256, 256>>>(dst);                              // 3
    gemm_f16<256><<<GG256, 256, SMEM>>>(pA, pBt, b0, pS, pG);          // 4 (profiled)

    // ---- CSR build remainder (3-kernel Blelloch scan: measured faster than
    //      single-pass lookback on this size) ----
    k_scan1<<<SCAN_BLOCKS, 256>>>();
    k_scan2<<<1, 512>>>();
    k_scan3<<<SCAN_BLOCKS, 256>>>();
    k_scatter<<<GRID_E256, 256>>>(src, dst);

    // ---- layer 0 tail ----
    k_agg_csr128_stats<<<AGG128_GRID, 256>>>(pG, pS, 0);
    k_bn_finalize<<<1, 128>>>(ga0, be0, 0);
    k_bn_relu_drop<<<DROP_GRID, 256>>>(pS, k00, k01);

    // ---- layer 1 ----
    gemm_f16<256><<<GG256, 256, SMEM>>>(pA, pBt + 32768, b1, pS, pG);
    k_agg_csr128_stats<<<AGG128_GRID, 256>>>(pG, pS, 1);
    k_bn_finalize<<<1, 128>>>(ga1, be1, 1);
    k_bn_relu_drop<<<DROP_GRID, 256>>>(pS, k10, k11);

    // ---- layer 2 (no BN / dropout), self-part straight to d_out ----
    gemm_f16<128><<<GG128, 256, SMEM>>>(pA, pBt + 65536, b2, out, pG);
    k_agg_csr64<<<AGG64_GRID, 256>>>(pG, out);
}

// round 17
// speedup vs baseline: 1.0270x; 1.0174x over previous
#include <cuda_runtime.h>
#include <cuda_fp16.h>
#include <cstdint>

#define NNODES 100000
#define NEDGES 1600000
#define NELEMS 12800000   // NNODES*128
#define SCAN_BLOCKS 391   // ceil(100000/256)
#define NSLICE 64

// ---------------- scratch (static device globals: allocation-free) ----------
__device__ float g_bufS[(size_t)NNODES * 128];   // self GEMM out / accumulator
__device__ __align__(16) __half g_G[(size_t)NNODES * 128];   // neigh GEMM out (fp16)
__device__ __align__(16) __half g_A[(size_t)NNODES * 128];   // activations fp16
__device__ __align__(16) __half g_Bt[3][256 * 128];  // per-layer [FCAT][128] fp16
__device__ int   g_degi[NNODES];
__device__ int   g_off[NNODES];
__device__ int   g_cursor[NNODES];
__device__ int   g_esrc[NEDGES];
__device__ int   g_bsum[512];
__device__ int   g_boff[512];
__device__ float g_psum[2][NSLICE * 128];   // per-layer BN partial sums
__device__ float g_psq[2][NSLICE * 128];
__device__ float g_scale[128];
__device__ float g_shift[128];

// ---------------- threefry2x32 (exact JAX implementation) -------------------
__host__ __device__ __forceinline__ void tf2x32(uint32_t k0, uint32_t k1,
                                                uint32_t& x0, uint32_t& x1)
{
    const uint32_t ks0 = k0, ks1 = k1, ks2 = k0 ^ k1 ^ 0x1BD11BDAu;
    const uint32_t ks[3] = {ks0, ks1, ks2};
    const int rot0[4] = {13, 15, 26, 6};
    const int rot1[4] = {17, 29, 16, 24};
    x0 += ks0; x1 += ks1;
#pragma unroll
    for (int b = 0; b < 5; b++) {
        const int* r = (b & 1) ? rot1 : rot0;
#pragma unroll
        for (int i = 0; i < 4; i++) {
            x0 += x1;
            x1 = (x1 << r[i]) | (x1 >> (32 - r[i]));
            x1 ^= x0;
        }
        x0 += ks[(b + 1) % 3];
        x1 += ks[(b + 2) % 3] + (uint32_t)(b + 1);
    }
}

// ---------------- convert x -> fp16, plus BN-partials zero-init --------------
__global__ void k_cvt_x(const float* __restrict__ x)
{
    int j2 = blockIdx.x * blockDim.x + threadIdx.x;
    if (j2 < 2 * NSLICE * 128) {
        ((float*)g_psum)[j2] = 0.f;
        ((float*)g_psq)[j2] = 0.f;
    }
    if (j2 >= NELEMS / 2) return;
    float2 v = __ldg((const float2*)x + j2);
    ((__half2*)g_A)[j2] = __halves2half2(__float2half_rn(v.x), __float2half_rn(v.y));
}

// ---------------- CSR build (runs on the side stream) ------------------------
__global__ void k_zero_deg()
{
    int i = blockIdx.x * blockDim.x + threadIdx.x;
    if (i < NNODES) g_degi[i] = 0;
}

__global__ void k_count_deg(const int* __restrict__ dst)
{
    int e = blockIdx.x * blockDim.x + threadIdx.x;
    if (e < NEDGES) atomicAdd(&g_degi[dst[e]], 1);
}

__global__ void k_scan1()
{
    __shared__ int sm[256];
    int b = blockIdx.x, t = threadIdx.x, i = b * 256 + t;
    int v = (i < NNODES) ? g_degi[i] : 0;
    sm[t] = v;
    __syncthreads();
#pragma unroll
    for (int d = 1; d < 256; d <<= 1) {
        int add = (t >= d) ? sm[t - d] : 0;
        __syncthreads();
        sm[t] += add;
        __syncthreads();
    }
    if (i < NNODES) g_off[i] = sm[t] - v;
    if (t == 255) g_bsum[b] = sm[255];
}

__global__ void k_scan2()
{
    __shared__ int sm[512];
    int t = threadIdx.x;
    int v = (t < SCAN_BLOCKS) ? g_bsum[t] : 0;
    sm[t] = v;
    __syncthreads();
#pragma unroll
    for (int d = 1; d < 512; d <<= 1) {
        int add = (t >= d) ? sm[t - d] : 0;
        __syncthreads();
        sm[t] += add;
        __syncthreads();
    }
    g_boff[t] = sm[t] - v;
}

__global__ void k_scan3()
{
    int i = blockIdx.x * blockDim.x + threadIdx.x;
    if (i < NNODES) {
        int o = g_off[i] + g_boff[i >> 8];
        g_off[i] = o;
        g_cursor[i] = o;
    }
}

__global__ void k_scatter(const int* __restrict__ src, const int* __restrict__ dst)
{
    int e = blockIdx.x * blockDim.x + threadIdx.x;
    if (e < NEDGES) {
        int p = atomicAdd(&g_cursor[dst[e]], 1);
        g_esrc[p] = src[e];
    }
}

// ---------------- all weight concats -> transposed fp16 (one kernel) --------
__global__ void k_cat_w_all(const float* __restrict__ Ws0, const float* __restrict__ Wn0,
                            const float* __restrict__ Ws1, const float* __restrict__ Wn1,
                            const float* __restrict__ Ws2, const float* __restrict__ Wn2)
{
    int i = blockIdx.x * blockDim.x + threadIdx.x;
    if (i >= 81920) return;   // 2*(32768) + 16384
    int L, base;
    if (i < 32768)      { L = 0; base = i; }
    else if (i < 65536) { L = 1; base = i - 32768; }
    else                { L = 2; base = i - 65536; }
    int c = base >> 7, k = base & 127;
    const float *Ws, *Wn;
    int F;
    if (L == 0)      { Ws = Ws0; Wn = Wn0; F = 128; }
    else if (L == 1) { Ws = Ws1; Wn = Wn1; F = 128; }
    else             { Ws = Ws2; Wn = Wn2; F = 64; }
    float w = (c < F) ? __ldg(&Ws[k * F + c]) : __ldg(&Wn[k * F + (c - F)]);
    g_Bt[L][c * 128 + k] = __float2half_rn(w);
}

// ---------------- tensor-core GEMM (fp16 operands, fp32 accumulate) ---------
__device__ __forceinline__ void ldsm_x4(uint32_t (&r)[4], uint32_t addr)
{
    asm volatile("ldmatrix.sync.aligned.m8n8.x4.shared.b16 {%0,%1,%2,%3}, [%4];\n"
                 : "=r"(r[0]), "=r"(r[1]), "=r"(r[2]), "=r"(r[3]) : "r"(addr));
}

__device__ __forceinline__ void mma_f16(float (&d)[4], const uint32_t (&a)[4],
                                        uint32_t b0, uint32_t b1)
{
    asm volatile("mma.sync.aligned.m16n8k16.row.col.f32.f16.f16.f32 "
                 "{%0,%1,%2,%3}, {%4,%5,%6,%7}, {%8,%9}, {%0,%1,%2,%3};\n"
                 : "+f"(d[0]), "+f"(d[1]), "+f"(d[2]), "+f"(d[3])
                 : "r"(a[0]), "r"(a[1]), "r"(a[2]), "r"(a[3]), "r"(b0), "r"(b1));
}

// C[N, FCAT] = A[N,128] @ Bt^T.  A fp16, B fp16, fp32 accumulate.
// Block: 128 rows x 64 cols, 8 warps (4m x 2n).
// Cols [0,FH) -> out1 fp32 (+bias); cols [FH,FCAT) -> outG fp16.
// smem = 34816 (A) + 17408 (B) = 52224B -> 3 CTAs/SM (@<=85 regs).
template <int FCAT>
__global__ void __launch_bounds__(256, 3)
gemm_f16(const __half* __restrict__ A, const __half* __restrict__ Bt,
         const float* __restrict__ bias,
         float* __restrict__ out1, __half* __restrict__ outG)
{
    constexpr int FH = FCAT / 2;
    extern __shared__ char sm[];
    const int tid = threadIdx.x;
    const int row0 = blockIdx.x * 128;
    const int col0 = blockIdx.y * 64;

    // stage A (128 rows x 128 k fp16) and B (64 n-rows x 128 k fp16)
    {
        const uint4* gA = (const uint4*)A;
        for (int idx = tid; idx < 2048; idx += 256) {
            int r = idx >> 4, c = idx & 15;
            int gr = row0 + r;
            uint4 v = make_uint4(0u, 0u, 0u, 0u);
            if (gr < NNODES) v = __ldg(gA + (size_t)gr * 16 + c);
            *(uint4*)(sm + r * 272 + c * 16) = v;
        }
        const uint4* gB = (const uint4*)Bt;
        for (int idx = tid; idx < 1024; idx += 256) {
            int r = idx >> 4, c = idx & 15;
            *(uint4*)(sm + 34816 + r * 272 + c * 16) = __ldg(gB + (size_t)(col0 + r) * 16 + c);
        }
    }
    __syncthreads();

    const int lane = tid & 31, wid = tid >> 5;
    const int m_base = (wid & 3) * 32, n_base = (wid >> 2) * 32;
    const int g = lane >> 3, rr = lane & 7;

    uint32_t smb = (uint32_t)__cvta_generic_to_shared(sm);
    const uint32_t sA = smb, sB = smb + 34816;

    uint32_t aoff[2], boff[2];
#pragma unroll
    for (int mt = 0; mt < 2; mt++) {
        int arow = m_base + mt * 16 + (g & 1) * 8 + rr;
        aoff[mt] = (uint32_t)(arow * 272 + (g >> 1) * 16);
    }
#pragma unroll
    for (int ng = 0; ng < 2; ng++) {
        int brow = n_base + ng * 16 + (g >> 1) * 8 + rr;
        boff[ng] = (uint32_t)(brow * 272 + (g & 1) * 16);
    }

    float acc[2][4][4];
#pragma unroll
    for (int mt = 0; mt < 2; mt++)
#pragma unroll
        for (int j = 0; j < 4; j++)
#pragma unroll
            for (int q = 0; q < 4; q++) acc[mt][j][q] = 0.f;

#pragma unroll
    for (int ks = 0; ks < 8; ks++) {
        const uint32_t kb = ks * 32;
        uint32_t a[2][4], bh[2][4];
        ldsm_x4(a[0], sA + aoff[0] + kb);
        ldsm_x4(a[1], sA + aoff[1] + kb);
        ldsm_x4(bh[0], sB + boff[0] + kb);
        ldsm_x4(bh[1], sB + boff[1] + kb);
#pragma unroll
        for (int mt = 0; mt < 2; mt++) {
#pragma unroll
            for (int j = 0; j < 4; j++) {
                const int ng = j >> 1, s = (j & 1) * 2;
                mma_f16(acc[mt][j], a[mt], bh[ng][s], bh[ng][s + 1]);
            }
        }
    }

    // store: block col range is entirely within out1 (fp32) or outG (fp16)
    const bool sel = (col0 < FH);
    const int cbase = col0 - (sel ? 0 : FH);
    const int tr = lane >> 2, tc = (lane & 3) * 2;

#pragma unroll
    for (int j = 0; j < 4; j++) {
        int gc = cbase + n_base + j * 8 + tc;
        float bx = 0.f, by = 0.f;
        if (sel) { bx = __ldg(bias + gc); by = __ldg(bias + gc + 1); }
#pragma unroll
        for (int mt = 0; mt < 2; mt++) {
            int r0g = row0 + m_base + mt * 16 + tr;
            if (r0g < NNODES) {
                if (sel) {
                    float2 v = make_float2(acc[mt][j][0] + bx, acc[mt][j][1] + by);
                    *(float2*)(out1 + (size_t)r0g * FH + gc) = v;
                } else {
                    *(__half2*)(outG + (size_t)r0g * FH + gc) =
                        __floats2half2_rn(acc[mt][j][0], acc[mt][j][1]);
                }
            }
            int r1g = r0g + 8;
            if (r1g < NNODES) {
                if (sel) {
                    float2 v = make_float2(acc[mt][j][2] + bx, acc[mt][j][3] + by);
                    *(float2*)(out1 + (size_t)r1g * FH + gc) = v;
                } else {
                    *(__half2*)(outG + (size_t)r1g * FH + gc) =
                        __floats2half2_rn(acc[mt][j][2], acc[mt][j][3]);
                }
            }
        }
    }
}

// ---------------- CSR aggregation fused with BN stats (F=128) ----------------
__global__ void __launch_bounds__(256)
k_agg_csr128_stats(const __half* __restrict__ G, float* __restrict__ S, int layer)
{
    __shared__ float sm_s[1024];   // [8 warps][128 feats]
    __shared__ float sm_q[1024];

    int gid = blockIdx.x * blockDim.x + threadIdx.x;
    int n = gid >> 4;              // always < NNODES (exact grid)
    int lane = threadIdx.x & 15;
    int cnt = g_degi[n];
    int beg = g_off[n];

    float a[8];
#pragma unroll
    for (int q = 0; q < 8; q++) a[q] = 0.f;

    for (int i = beg; i < beg + cnt; i++) {
        int s = __ldg(&g_esrc[i]);
        uint4 v = __ldg((const uint4*)(G + (size_t)s * 128) + lane);
        const __half2* hp = (const __half2*)&v;
#pragma unroll
        for (int q = 0; q < 4; q++) {
            float2 f = __half22float2(hp[q]);
            a[q * 2] += f.x;
            a[q * 2 + 1] += f.y;
        }
    }

    float4* p = (float4*)(S + (size_t)n * 128 + lane * 8);
    float4 c0 = p[0], c1 = p[1];
    if (cnt > 0) {
        float w = 1.0f / (float)cnt;
        c0.x = fmaf(a[0], w, c0.x); c0.y = fmaf(a[1], w, c0.y);
        c0.z = fmaf(a[2], w, c0.z); c0.w = fmaf(a[3], w, c0.w);
        c1.x = fmaf(a[4], w, c1.x); c1.y = fmaf(a[5], w, c1.y);
        c1.z = fmaf(a[6], w, c1.z); c1.w = fmaf(a[7], w, c1.w);
        p[0] = c0; p[1] = c1;
    }

    // BN stats: combine the 2 nodes per warp, stage per-warp slabs, reduce
    float sv[8] = {c0.x, c0.y, c0.z, c0.w, c1.x, c1.y, c1.z, c1.w};
    float qv[8];
#pragma unroll
    for (int q = 0; q < 8; q++) qv[q] = sv[q] * sv[q];
#pragma unroll
    for (int q = 0; q < 8; q++) {
        sv[q] += __shfl_xor_sync(0xffffffffu, sv[q], 16);
        qv[q] += __shfl_xor_sync(0xffffffffu, qv[q], 16);
    }
    int w = threadIdx.x >> 5;
    if ((threadIdx.x & 16) == 0) {
#pragma unroll
        for (int q = 0; q < 8; q++) {
            sm_s[w * 128 + lane * 8 + q] = sv[q];
            sm_q[w * 128 + lane * 8 + q] = qv[q];
        }
    }
    __syncthreads();
    if (threadIdx.x < 128) {
        float s = 0.f, q = 0.f;
#pragma unroll
        for (int ww = 0; ww < 8; ww++) {
            s += sm_s[ww * 128 + threadIdx.x];
            q += sm_q[ww * 128 + threadIdx.x];
        }
        int slice = blockIdx.x & (NSLICE - 1);
        atomicAdd(&g_psum[layer][slice * 128 + threadIdx.x], s);
        atomicAdd(&g_psq[layer][slice * 128 + threadIdx.x], q);
    }
}

// plain F=64 aggregation (no BN on layer 2). 8 lanes/node.
__global__ void __launch_bounds__(256)
k_agg_csr64(const __half* __restrict__ G, float* __restrict__ S)
{
    int gid = blockIdx.x * blockDim.x + threadIdx.x;
    int n = gid >> 3;
    if (n >= NNODES) return;
    int lane = threadIdx.x & 7;
    int cnt = g_degi[n];
    if (cnt == 0) return;
    int beg = g_off[n], end = beg + cnt;

    float a[8];
#pragma unroll
    for (int q = 0; q < 8; q++) a[q] = 0.f;

    for (int i = beg; i < end; i++) {
        int s = __ldg(&g_esrc[i]);
        uint4 v = __ldg((const uint4*)(G + (size_t)s * 64) + lane);
        const __half2* hp = (const __half2*)&v;
#pragma unroll
        for (int q = 0; q < 4; q++) {
            float2 f = __half22float2(hp[q]);
            a[q * 2] += f.x;
            a[q * 2 + 1] += f.y;
        }
    }
    float w = 1.0f / (float)cnt;
    float4* p = (float4*)(S + (size_t)n * 64 + lane * 8);
    float4 c0 = p[0], c1 = p[1];
    c0.x = fmaf(a[0], w, c0.x); c0.y = fmaf(a[1], w, c0.y);
    c0.z = fmaf(a[2], w, c0.z); c0.w = fmaf(a[3], w, c0.w);
    c1.x = fmaf(a[4], w, c1.x); c1.y = fmaf(a[5], w, c1.y);
    c1.z = fmaf(a[6], w, c1.z); c1.w = fmaf(a[7], w, c1.w);
    p[0] = c0; p[1] = c1;
}

// ---------------- batchnorm finalize ------------------------------------------
__global__ void k_bn_finalize(const float* __restrict__ gamma, const float* __restrict__ beta,
                              int layer)
{
    int f = threadIdx.x;
    float s = 0.f, q = 0.f;
#pragma unroll 8
    for (int w = 0; w < NSLICE; w++) {
        s += g_psum[layer][w * 128 + f];
        q += g_psq[layer][w * 128 + f];
    }
    float mu = s * (1.0f / NNODES);
    float var = fmaxf(q * (1.0f / NNODES) - mu * mu, 0.f);
    float sc = gamma[f] * rsqrtf(var + 1e-5f);
    g_scale[f] = sc;
    g_shift[f] = beta[f] - mu * sc;
}

// ---------------- fused BN * ReLU * dropout -> fp16 ---------------------------
__global__ void k_bn_relu_drop(const float* __restrict__ S,
                               uint32_t k0, uint32_t k1)
{
    int j2 = blockIdx.x * blockDim.x + threadIdx.x;
    if (j2 >= NELEMS / 2) return;
    int j = j2 * 2;
    uint32_t x0 = 0u, x1 = (uint32_t)j;
    tf2x32(k0, k1, x0, x1);
    uint32_t y0 = 0u, y1 = (uint32_t)(j + 1);
    tf2x32(k0, k1, y0, y1);
    int f = j & 127;
    float2 s = __ldg((const float2*)S + j2);
    float v0 = fmaxf(fmaf(s.x, g_scale[f], g_shift[f]), 0.f) * 2.0f;
    float v1 = fmaxf(fmaf(s.y, g_scale[f + 1], g_shift[f + 1]), 0.f) * 2.0f;
    v0 = ((x0 ^ x1) >> 31) ? v0 : 0.f;
    v1 = ((y0 ^ y1) >> 31) ? v1 : 0.f;
    ((__half2*)g_A)[j2] = __halves2half2(__float2half_rn(v0), __float2half_rn(v1));
}

// ---------------- driver -----------------------------------------------------
extern "C" void kernel_launch(void* const* d_in, const int* in_sizes, int n_in,
                              void* d_out, int out_size)
{
    const float* x   = (const float*)d_in[0];
    const int*   src = (const int*)d_in[1];
    const int*   dst = (const int*)d_in[2];
    const float* Ws0 = (const float*)d_in[3];
    const float* Wn0 = (const float*)d_in[4];
    const float* b0  = (const float*)d_in[5];
    const float* ga0 = (const float*)d_in[6];
    const float* be0 = (const float*)d_in[7];
    const float* Ws1 = (const float*)d_in[8];
    const float* Wn1 = (const float*)d_in[9];
    const float* b1  = (const float*)d_in[10];
    const float* ga1 = (const float*)d_in[11];
    const float* be1 = (const float*)d_in[12];
    const float* Ws2 = (const float*)d_in[13];
    const float* Wn2 = (const float*)d_in[14];
    const float* b2  = (const float*)d_in[15];
    float* out = (float*)d_out;

    // dropout keys (partitionable threefry, foldlike split)
    uint32_t k00 = 0u, k01 = 0u; tf2x32(0u, 42u, k00, k01);
    uint32_t k10 = 0u, k11 = 1u; tf2x32(0u, 42u, k10, k11);

    float *pS;
    __half *pA, *pG, *pBt;
    cudaGetSymbolAddress((void**)&pS, g_bufS);
    cudaGetSymbolAddress((void**)&pA, g_A);
    cudaGetSymbolAddress((void**)&pG, g_G);
    cudaGetSymbolAddress((void**)&pBt, g_Bt);

    const int SMEM = 52224;
    cudaFuncSetAttribute(gemm_f16<256>, cudaFuncAttributeMaxDynamicSharedMemorySize, SMEM);
    cudaFuncSetAttribute(gemm_f16<128>, cudaFuncAttributeMaxDynamicSharedMemorySize, SMEM);

    const int GRID_N256 = (NNODES + 255) / 256;
    const int GRID_E256 = (NEDGES + 255) / 256;
    const dim3 GG256((NNODES + 127) / 128, 4);
    const dim3 GG128((NNODES + 127) / 128, 2);
    const int AGG128_GRID = NNODES * 16 / 256;   // 6250, exact
    const int AGG64_GRID  = NNODES * 8 / 256;    // 3125, exact
    const int DROP_GRID = (NELEMS / 2 + 255) / 256;

    // Side stream + events for capturing the CSR build concurrently with the
    // front half (cvt_x / cat_w / gemm0). Created per call, intentionally not
    // destroyed (kernel_launch runs twice: correctness + capture).
    cudaStream_t s1;
    cudaStreamCreateWithFlags(&s1, cudaStreamNonBlocking);
    cudaEvent_t evFork, evJoin;
    cudaEventCreateWithFlags(&evFork, cudaEventDisableTiming);
    cudaEventCreateWithFlags(&evJoin, cudaEventDisableTiming);

    // fork: side stream joins the capture via an event from the main stream
    cudaEventRecord(evFork, 0);
    cudaStreamWaitEvent(s1, evFork, 0);

    // ---- side stream: full CSR build (independent of activations) ----
    k_zero_deg<<<GRID_N256, 256, 0, s1>>>();
    k_count_deg<<<GRID_E256, 256, 0, s1>>>(dst);
    k_scan1<<<SCAN_BLOCKS, 256, 0, s1>>>();
    k_scan2<<<1, 512, 0, s1>>>();
    k_scan3<<<SCAN_BLOCKS, 256, 0, s1>>>();
    k_scatter<<<GRID_E256, 256, 0, s1>>>(src, dst);
    cudaEventRecord(evJoin, s1);

    // ---- main stream: activation convert + weights + layer-0 GEMM ----
    k_cvt_x<<<DROP_GRID, 256>>>(x);
    k_cat_w_all<<<(81920 + 255) / 256, 256>>>(Ws0, Wn0, Ws1, Wn1, Ws2, Wn2);
    gemm_f16<256><<<GG256, 256, SMEM>>>(pA, pBt, b0, pS, pG);

    // join: aggregation needs the CSR
    cudaStreamWaitEvent(0, evJoin, 0);

    // ---- layer 0 tail ----
    k_agg_csr128_stats<<<AGG128_GRID, 256>>>(pG, pS, 0);
    k_bn_finalize<<<1, 128>>>(ga0, be0, 0);
    k_bn_relu_drop<<<DROP_GRID, 256>>>(pS, k00, k01);

    // ---- layer 1 ----
    gemm_f16<256><<<GG256, 256, SMEM>>>(pA, pBt + 32768, b1, pS, pG);
    k_agg_csr128_stats<<<AGG128_GRID, 256>>>(pG, pS, 1);
    k_bn_finalize<<<1, 128>>>(ga1, be1, 1);
    k_bn_relu_drop<<<DROP_GRID, 256>>>(pS, k10, k11);

    // ---- layer 2 (no BN / dropout), self-part straight to d_out ----
    gemm_f16<128><<<GG128, 256, SMEM>>>(pA, pBt + 65536, b2, out, pG);
    k_agg_csr64<<<AGG64_GRID, 256>>>(pG, out);
}